// round 15
// baseline (speedup 1.0000x reference)
#include <cuda_runtime.h>
#include <math.h>

#define N_    3072
#define E_    98304
#define CUM_  36
#define HID_  64
#define OUTD_ 5
#define NK9   (N_ * 9)
#define OUT_OFF (N_ * OUTD_)
#define RTILE 8
#define FULLW 0xffffffffu

// Scratch (device globals; no allocations allowed)
__device__ __align__(16) float g_A[N_ * 9];
__device__ __align__(16) float g_B[N_ * 9];
__device__ __align__(16) float g_feat[N_ * CUM_];   // [h1(9) | h2(27)] per node
__device__ __align__(16) float g_agg[N_ * CUM_];
__device__ int g_cnt[N_];
__device__ int g_cur[N_];
__device__ int g_offs[N_];
__device__ __align__(16) float4 g_epack[E_];        // {src(int bits), K0, K1, K2}

__device__ __forceinline__ float fast_tanh(float v) {
    float r;
    asm("tanh.approx.f32 %0, %1;" : "=f"(r) : "f"(v));
    return r;
}

// ---------------- R block body: rb in [0, 10368) ----------------
__device__ __forceinline__ void r_body(int rb, float* __restrict__ Rout) {
    __shared__ float sA[RTILE * 9];
    int tid = threadIdx.x;
    int tcol = rb % 27;
    int i0 = (rb / 27) * RTILE;
    if (tid < RTILE * 9) sA[tid] = g_A[i0 * 9 + tid];
    __syncthreads();
    int t0 = (tcol * 256 + tid) * 4;
    float4 b = *reinterpret_cast<const float4*>(&g_B[t0]);
    int k0 = t0 % 9;
    int k1 = k0 + 1; if (k1 >= 9) k1 -= 9;
    int k2 = k1 + 1; if (k2 >= 9) k2 -= 9;
    int k3 = k2 + 1; if (k3 >= 9) k3 -= 9;
#pragma unroll
    for (int r = 0; r < RTILE; r++) {
        const float* a = &sA[r * 9];
        float4 v;
        v.x = fast_tanh(a[k0] + b.x);
        v.y = fast_tanh(a[k1] + b.y);
        v.z = fast_tanh(a[k2] + b.z);
        v.w = fast_tanh(a[k3] + b.w);
        __stcs(reinterpret_cast<float4*>(Rout + (size_t)(i0 + r) * NK9 + t0), v);
    }
}

// ---------------- k0: zero counters || sheaf factors A,B ----------------
// 132 blocks: [0,24) zero cnt+cur (6144 ints), [24,132) ab (27648 elems)
__global__ void k0_init(const float* __restrict__ x,
                        const float* __restrict__ Ws,
                        const float* __restrict__ bs) {
    int bid = blockIdx.x;
    if (bid < 24) {
        int i = bid * 256 + threadIdx.x;
        if (i < N_) g_cnt[i] = 0; else g_cur[i - N_] = 0;
    } else {
        int idx = (bid - 24) * 256 + threadIdx.x;   // < N*9 exactly
        int i = idx / 9, k = idx - 9 * i;
        float x0 = x[i * 3 + 0], x1 = x[i * 3 + 1], x2 = x[i * 3 + 2];
        g_A[idx] = x0 * Ws[k] + x1 * Ws[9 + k] + x2 * Ws[18 + k] + bs[k];
        g_B[idx] = x0 * Ws[27 + k] + x1 * Ws[36 + k] + x2 * Ws[45 + k];
    }
}

// ---------------- kA: count edges per target || R [0,1152) ----------------
__global__ void kA_count_R(const int* __restrict__ ei, float* __restrict__ Rout) {
    int bid = blockIdx.x;                  // 1536
    if ((bid & 3) == 0) {
        int e = (bid >> 2) * 256 + threadIdx.x;   // 384*256 = E exact
        atomicAdd(&g_cnt[ei[E_ + e]], 1);
    } else {
        r_body(bid - (bid >> 2) - 1, Rout);
    }
}

// ---------------- kS: exclusive prefix scan (block 0) || R [1152,1536) -----
__global__ void kS_scan_R(float* __restrict__ Rout) {
    int bid = blockIdx.x;                  // 385
    if (bid == 0) {
        __shared__ int s_sum[256];
        int tid = threadIdx.x;
        int base = tid * 12;
        int c[12], run = 0;
#pragma unroll
        for (int j = 0; j < 12; j++) { c[j] = g_cnt[base + j]; run += c[j]; }
        s_sum[tid] = run;
        __syncthreads();
        for (int off = 1; off < 256; off <<= 1) {
            int v = (tid >= off) ? s_sum[tid - off] : 0;
            __syncthreads();
            s_sum[tid] += v;
            __syncthreads();
        }
        int excl = s_sum[tid] - run;
#pragma unroll
        for (int j = 0; j < 12; j++) { g_offs[base + j] = excl; excl += c[j]; }
    } else {
        r_body(1152 + bid - 1, Rout);
    }
}

// ---------------- kB: fill packed edge slots || R [1536,2688) ----------------
__global__ void kB_fill_R(const int* __restrict__ ei, const float* __restrict__ K,
                          float* __restrict__ Rout) {
    int bid = blockIdx.x;                  // 1536
    if ((bid & 3) == 0) {
        int e = (bid >> 2) * 256 + threadIdx.x;
        int s = ei[e], t = ei[E_ + e];
        int slot = g_offs[t] + atomicAdd(&g_cur[t], 1);
        g_epack[slot] = make_float4(__int_as_float(s), K[e], K[E_ + e], K[2 * E_ + e]);
    } else {
        r_body(1536 + bid - (bid >> 2) - 1, Rout);
    }
}

// ---------------- k1: g1 gather (warp/node) || R [2688,4608) ----------------
__global__ void k1_g1_R(const float* __restrict__ x, float* __restrict__ Rout) {
    int bid = blockIdx.x;                  // 2304
    if (bid % 6 == 0) {
        int lane = threadIdx.x & 31;
        int t = (bid / 6) * 8 + (threadIdx.x >> 5);   // 384*8 = N exact
        int beg = g_offs[t], cnt = g_cnt[t];
        float a[9] = {0,0,0,0,0,0,0,0,0};
        for (int p = lane; p < cnt; p += 32) {
            float4 ep = g_epack[beg + p];
            int s = __float_as_int(ep.x);
            float x0 = x[3 * s], x1 = x[3 * s + 1], x2 = x[3 * s + 2];
            a[0] += ep.y * x0; a[1] += ep.y * x1; a[2] += ep.y * x2;
            a[3] += ep.z * x0; a[4] += ep.z * x1; a[5] += ep.z * x2;
            a[6] += ep.w * x0; a[7] += ep.w * x1; a[8] += ep.w * x2;
        }
#pragma unroll
        for (int j = 0; j < 9; j++)
#pragma unroll
            for (int o = 16; o > 0; o >>= 1) a[j] += __shfl_xor_sync(FULLW, a[j], o);
        if (lane == 0) {
            float* d = &g_feat[t * CUM_];
#pragma unroll
            for (int j = 0; j < 9; j++) d[j] = a[j];
        }
    } else {
        r_body(2688 + bid - bid / 6 - 1, Rout);
    }
}

// ---------------- k2: g2 gather (warp/node) || R [4608,7296) ----------------
__global__ void k2_g2_R(float* __restrict__ Rout) {
    int bid = blockIdx.x;                  // 3072
    if ((bid & 7) == 0) {
        int lane = threadIdx.x & 31;
        int t = (bid >> 3) * 8 + (threadIdx.x >> 5);
        int beg = g_offs[t], cnt = g_cnt[t];
        float a[27];
#pragma unroll
        for (int j = 0; j < 27; j++) a[j] = 0.f;
        for (int p = lane; p < cnt; p += 32) {
            float4 ep = g_epack[beg + p];
            int s = __float_as_int(ep.x);
            const float* hr = &g_feat[s * CUM_];
            float4 h0 = *reinterpret_cast<const float4*>(hr);
            float4 h1 = *reinterpret_cast<const float4*>(hr + 4);
            float h8 = hr[8];
            float hj[9] = {h0.x, h0.y, h0.z, h0.w, h1.x, h1.y, h1.z, h1.w, h8};
#pragma unroll
            for (int j = 0; j < 9; j++) {
                a[j]      += ep.y * hj[j];
                a[9 + j]  += ep.z * hj[j];
                a[18 + j] += ep.w * hj[j];
            }
        }
#pragma unroll
        for (int j = 0; j < 27; j++)
#pragma unroll
            for (int o = 16; o > 0; o >>= 1) a[j] += __shfl_xor_sync(FULLW, a[j], o);
        if (lane == 0) {
            float* d = &g_feat[t * CUM_ + 9];
#pragma unroll
            for (int j = 0; j < 27; j++) d[j] = a[j];
        }
    } else {
        r_body(4608 + bid - (bid >> 3) - 1, Rout);
    }
}

// ---------------- k3: agg gather (warp/node) || R [7296,10368) ----------------
__global__ void k3_agg_R(float* __restrict__ Rout) {
    int bid = blockIdx.x;                  // 3456
    if (bid % 9 == 0) {
        int lane = threadIdx.x & 31;
        int t = (bid / 9) * 8 + (threadIdx.x >> 5);
        int beg = g_offs[t], cnt = g_cnt[t];
        float a[36];
#pragma unroll
        for (int j = 0; j < 36; j++) a[j] = 0.f;
        for (int p = lane; p < cnt; p += 32) {
            float4 ep = g_epack[beg + p];
            int s = __float_as_int(ep.x);
            const float4* fr = reinterpret_cast<const float4*>(&g_feat[s * CUM_]);
#pragma unroll
            for (int q = 0; q < 9; q++) {
                float4 v = fr[q];
                a[q * 4 + 0] += v.x; a[q * 4 + 1] += v.y;
                a[q * 4 + 2] += v.z; a[q * 4 + 3] += v.w;
            }
        }
#pragma unroll
        for (int j = 0; j < 36; j++)
#pragma unroll
            for (int o = 16; o > 0; o >>= 1) a[j] += __shfl_xor_sync(FULLW, a[j], o);
        if (lane == 0) {
            float4* d = reinterpret_cast<float4*>(&g_agg[t * CUM_]);
#pragma unroll
            for (int q = 0; q < 9; q++)
                d[q] = make_float4(a[q * 4], a[q * 4 + 1], a[q * 4 + 2], a[q * 4 + 3]);
        }
    } else {
        r_body(7296 + bid - bid / 9 - 1, Rout);
    }
}

// ---------------- head: conv(36->36)+MLP(36->64->5) ----------------
__global__ void k_head(const float* __restrict__ Wc, const float* __restrict__ bc,
                       const float* __restrict__ W1, const float* __restrict__ b1,
                       const float* __restrict__ W2, const float* __restrict__ b2,
                       float* __restrict__ out) {
    int i = blockIdx.x;
    int o = threadIdx.x;                 // 0..63
    __shared__ float s_in[CUM_];
    __shared__ float s_conv[CUM_];
    __shared__ float s_hid[HID_];

    float inv = 1.f / fmaxf((float)g_cnt[i], 1.f);
    if (o < CUM_) s_in[o] = g_agg[i * CUM_ + o] * inv;
    __syncthreads();

    if (o < CUM_) {
        float acc = bc[o];
#pragma unroll
        for (int c = 0; c < CUM_; c++) acc += s_in[c] * Wc[c * CUM_ + o];
        s_conv[o] = fmaxf(acc, 0.f);
    }
    __syncthreads();

    {
        float acc = b1[o];
#pragma unroll
        for (int c = 0; c < CUM_; c++) acc += s_conv[c] * W1[c * HID_ + o];
        s_hid[o] = fmaxf(acc, 0.f);
    }
    __syncthreads();

    if (o < OUTD_) {
        float acc = b2[o];
#pragma unroll
        for (int c = 0; c < HID_; c++) acc += s_hid[c] * W2[c * OUTD_ + o];
        out[i * OUTD_ + o] = acc;
    }
}

extern "C" void kernel_launch(void* const* d_in, const int* in_sizes, int n_in,
                              void* d_out, int out_size) {
    const float* x  = (const float*)d_in[0];
    const int*   ei = (const int*)d_in[1];     // int32 (JAX x64 disabled)
    const float* K  = (const float*)d_in[2];
    const float* Ws = (const float*)d_in[3];
    const float* bs = (const float*)d_in[4];
    const float* Wc = (const float*)d_in[5];
    const float* bc = (const float*)d_in[6];
    const float* W1 = (const float*)d_in[7];
    const float* b1 = (const float*)d_in[8];
    const float* W2 = (const float*)d_in[9];
    const float* b2 = (const float*)d_in[10];
    float* out = (float*)d_out;
    float* R   = out + OUT_OFF;

    k0_init<<<132, 256>>>(x, Ws, bs);
    kA_count_R<<<1536, 256>>>(ei, R);
    kS_scan_R<<<385, 256>>>(R);
    kB_fill_R<<<1536, 256>>>(ei, K, R);
    k1_g1_R<<<2304, 256>>>(x, R);
    k2_g2_R<<<3072, 256>>>(R);
    k3_agg_R<<<3456, 256>>>(R);
    k_head<<<N_, HID_>>>(Wc, bc, W1, b1, W2, b2, out);
}

// round 16
// speedup vs baseline: 1.1199x; 1.1199x over previous
#include <cuda_runtime.h>
#include <math.h>

#define N_    3072
#define E_    98304
#define CUM_  36
#define HID_  64
#define OUTD_ 5
#define NK9   (N_ * 9)
#define OUT_OFF (N_ * OUTD_)
#define RTILE 8
#define ROW   48            // padded feature row (floats): h1 k*4+j (deg @3), h2 12+k*12+j

// Scratch (device globals; no allocations allowed)
__device__ __align__(16) float g_A[N_ * 9];
__device__ __align__(16) float g_B[N_ * 9];
__device__ __align__(16) float g_feat[N_ * ROW];
__device__ __align__(16) float g_agg[N_ * ROW];

__device__ __forceinline__ float fast_tanh(float v) {
    float r;
    asm("tanh.approx.f32 %0, %1;" : "=f"(r) : "f"(v));
    return r;
}
__device__ __forceinline__ void red_add_v4(float* ptr, float a, float b, float c, float d) {
    asm volatile("red.global.add.v4.f32 [%0], {%1, %2, %3, %4};"
                 :: "l"(ptr), "f"(a), "f"(b), "f"(c), "f"(d) : "memory");
}
__device__ __forceinline__ void red_add_f(float* ptr, float a) {
    asm volatile("red.global.add.f32 [%0], %1;" :: "l"(ptr), "f"(a) : "memory");
}

// ---------------- R block body: rb in [0, 10368) ----------------
__device__ __forceinline__ void r_body(int rb, float* __restrict__ Rout) {
    __shared__ float sA[RTILE * 9];
    int tid = threadIdx.x;
    int tcol = rb % 27;
    int i0 = (rb / 27) * RTILE;
    if (tid < RTILE * 9) sA[tid] = g_A[i0 * 9 + tid];
    __syncthreads();
    int t0 = (tcol * 256 + tid) * 4;
    float4 b = *reinterpret_cast<const float4*>(&g_B[t0]);
    int k0 = t0 % 9;
    int k1 = k0 + 1; if (k1 >= 9) k1 -= 9;
    int k2 = k1 + 1; if (k2 >= 9) k2 -= 9;
    int k3 = k2 + 1; if (k3 >= 9) k3 -= 9;
#pragma unroll
    for (int r = 0; r < RTILE; r++) {
        const float* a = &sA[r * 9];
        float4 v;
        v.x = fast_tanh(a[k0] + b.x);
        v.y = fast_tanh(a[k1] + b.y);
        v.z = fast_tanh(a[k2] + b.z);
        v.w = fast_tanh(a[k3] + b.w);
        __stcs(reinterpret_cast<float4*>(Rout + (size_t)(i0 + r) * NK9 + t0), v);
    }
}

// ---------------- k0: zero feat/agg (float4) || sheaf factors A,B ----------
// 396 blocks: [0,288) zero (73728 float4), [288,396) ab (27648 elems)
__global__ void k0_init(const float* __restrict__ x,
                        const float* __restrict__ Ws,
                        const float* __restrict__ bs) {
    int bid = blockIdx.x;
    if (bid < 288) {
        int i = bid * 256 + threadIdx.x;            // < 73728
        const int HALF = N_ * ROW / 4;              // 36864
        float4 z = make_float4(0.f, 0.f, 0.f, 0.f);
        if (i < HALF) reinterpret_cast<float4*>(g_feat)[i] = z;
        else          reinterpret_cast<float4*>(g_agg)[i - HALF] = z;
    } else {
        int idx = (bid - 288) * 256 + threadIdx.x;  // < N*9 exactly
        int i = idx / 9, k = idx - 9 * i;
        float x0 = x[i * 3 + 0], x1 = x[i * 3 + 1], x2 = x[i * 3 + 2];
        g_A[idx] = x0 * Ws[k] + x1 * Ws[9 + k] + x2 * Ws[18 + k] + bs[k];
        g_B[idx] = x0 * Ws[27 + k] + x1 * Ws[36 + k] + x2 * Ws[45 + k];
    }
}

// ---------------- k1: g1 (1152) || R [0,2304), 1:2 ----------------
__global__ void k1_g1_R(const float* __restrict__ x,
                        const int* __restrict__ ei,
                        const float* __restrict__ K,
                        float* __restrict__ Rout) {
    int bid = blockIdx.x;                 // 3456
    if (bid % 3 == 0) {
        int idx = (bid / 3) * 256 + threadIdx.x;    // < 3E exactly
        int k = idx / E_, e = idx - k * E_;
        int s = ei[e], t = ei[E_ + e];
        float kv = K[k * E_ + e];
        float x0 = x[3 * s], x1 = x[3 * s + 1], x2 = x[3 * s + 2];
        float w = (k == 0) ? 1.f : 0.f;             // deg in pad lane 3
        red_add_v4(&g_feat[t * ROW + k * 4], kv * x0, kv * x1, kv * x2, w);
    } else {
        r_body(bid - bid / 3 - 1, Rout);
    }
}

// ---------------- k2: g2 (1152) || R [2304,4608), 1:2 ----------------
__global__ void k2_g2_R(const int* __restrict__ ei,
                        const float* __restrict__ K,
                        float* __restrict__ Rout) {
    int bid = blockIdx.x;                 // 3456
    if (bid % 3 == 0) {
        int idx = (bid / 3) * 256 + threadIdx.x;    // < 3E exactly
        int k = idx / E_, e = idx - k * E_;
        int s = ei[e], t = ei[E_ + e];
        float kv = K[k * E_ + e];
        const float4* hr = reinterpret_cast<const float4*>(&g_feat[s * ROW]);
        float4 q0 = hr[0], q1 = hr[1], q2 = hr[2];  // h1 channels in xyz lanes
        float* base = &g_feat[t * ROW + 12 + k * 12];
        red_add_v4(base,     kv * q0.x, kv * q0.y, kv * q0.z, kv * q1.x);
        red_add_v4(base + 4, kv * q1.y, kv * q1.z, kv * q2.x, kv * q2.y);
        red_add_f(base + 8, kv * q2.z);
    } else {
        r_body(2304 + bid - bid / 3 - 1, Rout);
    }
}

// ---------------- k3: agg (2304) || R [4608,6912), 1:1 ----------------
__global__ void k3_agg_R(const int* __restrict__ ei,
                         float* __restrict__ Rout) {
    int bid = blockIdx.x;                 // 4608
    if ((bid & 1) == 0) {
        int idx = (bid >> 1) * 256 + threadIdx.x;   // < 6E exactly
        int e = idx / 6, gp = idx - 6 * e;          // 2 float4 groups per thread
        int s = ei[e], t = ei[E_ + e];
        const float4* fr = reinterpret_cast<const float4*>(&g_feat[s * ROW]);
        float4 v0 = fr[2 * gp], v1 = fr[2 * gp + 1];
        red_add_v4(&g_agg[t * ROW + 8 * gp],     v0.x, v0.y, v0.z, v0.w);
        red_add_v4(&g_agg[t * ROW + 8 * gp + 4], v1.x, v1.y, v1.z, v1.w);
    } else {
        r_body(4608 + (bid >> 1), Rout);
    }
}

// map reference channel c (0..35) -> padded row position
__device__ __forceinline__ int chan_pos(int c) {
    if (c < 9) return (c / 3) * 4 + (c % 3);
    int j = c - 9;
    return 12 + (j / 9) * 12 + (j % 9);
}

// ---------------- k4: head (768 blocks x 4 nodes) || R [6912,10368), 2:9 ----
__global__ void k4_head_R(const float* __restrict__ Wc, const float* __restrict__ bc,
                          const float* __restrict__ W1, const float* __restrict__ b1,
                          const float* __restrict__ W2, const float* __restrict__ b2,
                          float* __restrict__ out, float* __restrict__ Rout) {
    int bid = blockIdx.x;                 // 4224 = 384 * 11 : per 11 -> 2 head + 9 R
    int grp = bid / 11, rem = bid - grp * 11;
    if (rem < 2) {
        int cidx = grp * 2 + rem;                   // [0,768)
        int tid = threadIdx.x;
        int sub = tid >> 6, o = tid & 63;           // 4 nodes / block
        int node = cidx * 4 + sub;
        __shared__ float s_in[4][CUM_];
        __shared__ float s_conv[4][CUM_];
        __shared__ float s_hid[4][HID_];

        float deg = g_feat[node * ROW + 3];         // count folded into pad lane
        float inv = 1.f / fmaxf(deg, 1.f);
        if (o < CUM_) s_in[sub][o] = g_agg[node * ROW + chan_pos(o)] * inv;
        __syncthreads();

        if (o < CUM_) {
            float acc = bc[o];
#pragma unroll
            for (int c = 0; c < CUM_; c++) acc += s_in[sub][c] * Wc[c * CUM_ + o];
            s_conv[sub][o] = fmaxf(acc, 0.f);
        }
        __syncthreads();

        {
            float acc = b1[o];
#pragma unroll
            for (int c = 0; c < CUM_; c++) acc += s_conv[sub][c] * W1[c * HID_ + o];
            s_hid[sub][o] = fmaxf(acc, 0.f);
        }
        __syncthreads();

        if (o < OUTD_) {
            float acc = b2[o];
#pragma unroll
            for (int c = 0; c < HID_; c++) acc += s_hid[sub][c] * W2[c * OUTD_ + o];
            out[node * OUTD_ + o] = acc;
        }
    } else {
        r_body(6912 + grp * 9 + (rem - 2), Rout);
    }
}

extern "C" void kernel_launch(void* const* d_in, const int* in_sizes, int n_in,
                              void* d_out, int out_size) {
    const float* x  = (const float*)d_in[0];
    const int*   ei = (const int*)d_in[1];     // int32 (JAX x64 disabled)
    const float* K  = (const float*)d_in[2];
    const float* Ws = (const float*)d_in[3];
    const float* bs = (const float*)d_in[4];
    const float* Wc = (const float*)d_in[5];
    const float* bc = (const float*)d_in[6];
    const float* W1 = (const float*)d_in[7];
    const float* b1 = (const float*)d_in[8];
    const float* W2 = (const float*)d_in[9];
    const float* b2 = (const float*)d_in[10];
    float* out = (float*)d_out;
    float* R   = out + OUT_OFF;

    k0_init<<<396, 256>>>(x, Ws, bs);
    k1_g1_R<<<3456, 256>>>(x, ei, K, R);
    k2_g2_R<<<3456, 256>>>(ei, K, R);
    k3_agg_R<<<4608, 256>>>(ei, R);
    k4_head_R<<<4224, 256>>>(Wc, bc, W1, b1, W2, b2, out, R);
}

// round 17
// speedup vs baseline: 1.1281x; 1.0074x over previous
#include <cuda_runtime.h>
#include <math.h>

#define N_    3072
#define E_    98304
#define CUM_  36
#define HID_  64
#define OUTD_ 5
#define NK9   (N_ * 9)
#define OUT_OFF (N_ * OUTD_)
#define RTILE 8
#define ROW   48            // padded feature row: h1 k*4+j (deg @3), h2 12+k*12+j

// Scratch (device globals; zero-initialized at module load; every call
// restores them to zero after use -> no init kernel needed)
__device__ __align__(16) float g_feat[N_ * ROW];
__device__ __align__(16) float g_agg[N_ * ROW];

__device__ __forceinline__ float fast_tanh(float v) {
    float r;
    asm("tanh.approx.f32 %0, %1;" : "=f"(r) : "f"(v));
    return r;
}
__device__ __forceinline__ void red_add_v4(float* ptr, float a, float b, float c, float d) {
    asm volatile("red.global.add.v4.f32 [%0], {%1, %2, %3, %4};"
                 :: "l"(ptr), "f"(a), "f"(b), "f"(c), "f"(d) : "memory");
}
__device__ __forceinline__ void red_add_f(float* ptr, float a) {
    asm volatile("red.global.add.f32 [%0], %1;" :: "l"(ptr), "f"(a) : "memory");
}

// ---------------- R block body: rb in [0, 10368) ----------------
// Fully self-contained: computes sheaf factors A (8 rows, smem) and B
// (4 per thread, regs) inline from x/Ws/bs. No dependency on any prior kernel.
__device__ __forceinline__ void r_body(int rb, const float* __restrict__ x,
                                       const float* __restrict__ Ws,
                                       const float* __restrict__ bs,
                                       float* __restrict__ Rout) {
    __shared__ float sW[63];            // 54 W_sheaf + 9 bias
    __shared__ float sA[RTILE * 9];
    int tid = threadIdx.x;
    int tcol = rb % 27;
    int i0 = (rb / 27) * RTILE;
    if (tid < 63) sW[tid] = (tid < 54) ? Ws[tid] : bs[tid - 54];
    __syncthreads();
    if (tid < RTILE * 9) {
        int r = tid / 9, k = tid - 9 * r;
        int i = i0 + r;
        float x0 = x[3 * i], x1 = x[3 * i + 1], x2 = x[3 * i + 2];
        sA[tid] = x0 * sW[k] + x1 * sW[9 + k] + x2 * sW[18 + k] + sW[54 + k];
    }
    __syncthreads();

    int t0 = (tcol * 256 + tid) * 4;
    int k0 = t0 % 9;
    int k1 = k0 + 1; if (k1 >= 9) k1 -= 9;
    int k2 = k1 + 1; if (k2 >= 9) k2 -= 9;
    int k3 = k2 + 1; if (k3 >= 9) k3 -= 9;
    // B values for the 4 elements: j = t/9 spans at most 2 source rows
    int j0 = t0 / 9, j1 = (t0 + 3) / 9;
    float xa0 = x[3 * j0], xa1 = x[3 * j0 + 1], xa2 = x[3 * j0 + 2];
    float xb0 = x[3 * j1], xb1 = x[3 * j1 + 1], xb2 = x[3 * j1 + 2];
    int split = j1 * 9 - t0;            // element m uses row j1 iff m >= split
    int kk[4] = {k0, k1, k2, k3};
    float B[4];
#pragma unroll
    for (int m = 0; m < 4; m++) {
        int k = kk[m];
        float r0 = (m >= split) ? xb0 : xa0;
        float r1 = (m >= split) ? xb1 : xa1;
        float r2 = (m >= split) ? xb2 : xa2;
        B[m] = r0 * sW[27 + k] + r1 * sW[36 + k] + r2 * sW[45 + k];
    }
#pragma unroll
    for (int r = 0; r < RTILE; r++) {
        const float* a = &sA[r * 9];
        float4 v;
        v.x = fast_tanh(a[k0] + B[0]);
        v.y = fast_tanh(a[k1] + B[1]);
        v.z = fast_tanh(a[k2] + B[2]);
        v.w = fast_tanh(a[k3] + B[3]);
        __stcs(reinterpret_cast<float4*>(Rout + (size_t)(i0 + r) * NK9 + t0), v);
    }
}

// ---------------- k1: g1 (1152) || R [0,3072), 3:8 ----------------
__global__ void k1_g1_R(const float* __restrict__ x,
                        const int* __restrict__ ei,
                        const float* __restrict__ K,
                        const float* __restrict__ Ws,
                        const float* __restrict__ bs,
                        float* __restrict__ Rout) {
    int bid = blockIdx.x;                 // 4224 = 384 * 11
    int grp = bid / 11, rem = bid - grp * 11;
    if (rem < 3) {
        int idx = (grp * 3 + rem) * 256 + threadIdx.x;   // < 3E exactly
        int k = idx / E_, e = idx - k * E_;
        int s = ei[e], t = ei[E_ + e];
        float kv = K[k * E_ + e];
        float x0 = x[3 * s], x1 = x[3 * s + 1], x2 = x[3 * s + 2];
        float w = (k == 0) ? 1.f : 0.f;                  // deg in pad lane 3
        red_add_v4(&g_feat[t * ROW + k * 4], kv * x0, kv * x1, kv * x2, w);
    } else {
        r_body(grp * 8 + (rem - 3), x, Ws, bs, Rout);
    }
}

// ---------------- k2: g2 (1152) || R [3072,6144), 3:8 ----------------
__global__ void k2_g2_R(const float* __restrict__ x,
                        const int* __restrict__ ei,
                        const float* __restrict__ K,
                        const float* __restrict__ Ws,
                        const float* __restrict__ bs,
                        float* __restrict__ Rout) {
    int bid = blockIdx.x;                 // 4224
    int grp = bid / 11, rem = bid - grp * 11;
    if (rem < 3) {
        int idx = (grp * 3 + rem) * 256 + threadIdx.x;   // < 3E exactly
        int k = idx / E_, e = idx - k * E_;
        int s = ei[e], t = ei[E_ + e];
        float kv = K[k * E_ + e];
        const float4* hr = reinterpret_cast<const float4*>(&g_feat[s * ROW]);
        float4 q0 = hr[0], q1 = hr[1], q2 = hr[2];       // h1 in xyz lanes
        float* base = &g_feat[t * ROW + 12 + k * 12];
        red_add_v4(base,     kv * q0.x, kv * q0.y, kv * q0.z, kv * q1.x);
        red_add_v4(base + 4, kv * q1.y, kv * q1.z, kv * q2.x, kv * q2.y);
        red_add_f(base + 8, kv * q2.z);
    } else {
        r_body(3072 + grp * 8 + (rem - 3), x, Ws, bs, Rout);
    }
}

// ---------------- k3: agg (2304) || R [6144,8448), 1:1 ----------------
__global__ void k3_agg_R(const float* __restrict__ x,
                         const int* __restrict__ ei,
                         const float* __restrict__ Ws,
                         const float* __restrict__ bs,
                         float* __restrict__ Rout) {
    int bid = blockIdx.x;                 // 4608
    if ((bid & 1) == 0) {
        int idx = (bid >> 1) * 256 + threadIdx.x;        // < 6E exactly
        int e = idx / 6, gp = idx - 6 * e;
        int s = ei[e], t = ei[E_ + e];
        const float4* fr = reinterpret_cast<const float4*>(&g_feat[s * ROW]);
        float4 v0 = fr[2 * gp], v1 = fr[2 * gp + 1];
        red_add_v4(&g_agg[t * ROW + 8 * gp],     v0.x, v0.y, v0.z, v0.w);
        red_add_v4(&g_agg[t * ROW + 8 * gp + 4], v1.x, v1.y, v1.z, v1.w);
    } else {
        r_body(6144 + (bid >> 1), x, Ws, bs, Rout);
    }
}

// map reference channel c (0..35) -> padded row position
__device__ __forceinline__ int chan_pos(int c) {
    if (c < 9) return (c / 3) * 4 + (c % 3);
    int j = c - 9;
    return 12 + (j / 9) * 12 + (j % 9);
}

// ---------------- k4: head (768 x 4 nodes) || R [8448,10368), 2:5 ----------
// Head blocks also RESTORE g_feat/g_agg rows to zero after consuming them,
// maintaining the all-zero invariant for the next call.
__global__ void k4_head_R(const float* __restrict__ x,
                          const float* __restrict__ Wc, const float* __restrict__ bc,
                          const float* __restrict__ W1, const float* __restrict__ b1,
                          const float* __restrict__ W2, const float* __restrict__ b2,
                          const float* __restrict__ Ws, const float* __restrict__ bs,
                          float* __restrict__ out, float* __restrict__ Rout) {
    int bid = blockIdx.x;                 // 2688 = 384 * 7
    int grp = bid / 7, rem = bid - grp * 7;
    if (rem < 2) {
        int cidx = grp * 2 + rem;                        // [0,768)
        int tid = threadIdx.x;
        int sub = tid >> 6, o = tid & 63;                // 4 nodes / block
        int node = cidx * 4 + sub;
        __shared__ float s_in[4][CUM_];
        __shared__ float s_conv[4][CUM_];
        __shared__ float s_hid[4][HID_];

        float deg = g_feat[node * ROW + 3];              // count in pad lane
        float inv = 1.f / fmaxf(deg, 1.f);
        if (o < CUM_) s_in[sub][o] = g_agg[node * ROW + chan_pos(o)] * inv;
        __syncthreads();

        // restore the zero invariant (reads above are done)
        if (o < 12) {
            float4 z = make_float4(0.f, 0.f, 0.f, 0.f);
            reinterpret_cast<float4*>(&g_feat[node * ROW])[o] = z;
            reinterpret_cast<float4*>(&g_agg[node * ROW])[o] = z;
        }

        if (o < CUM_) {
            float acc = bc[o];
#pragma unroll
            for (int c = 0; c < CUM_; c++) acc += s_in[sub][c] * Wc[c * CUM_ + o];
            s_conv[sub][o] = fmaxf(acc, 0.f);
        }
        __syncthreads();

        {
            float acc = b1[o];
#pragma unroll
            for (int c = 0; c < CUM_; c++) acc += s_conv[sub][c] * W1[c * HID_ + o];
            s_hid[sub][o] = fmaxf(acc, 0.f);
        }
        __syncthreads();

        if (o < OUTD_) {
            float acc = b2[o];
#pragma unroll
            for (int c = 0; c < HID_; c++) acc += s_hid[sub][c] * W2[c * OUTD_ + o];
            out[node * OUTD_ + o] = acc;
        }
    } else {
        r_body(8448 + grp * 5 + (rem - 2), x, Ws, bs, Rout);
    }
}

extern "C" void kernel_launch(void* const* d_in, const int* in_sizes, int n_in,
                              void* d_out, int out_size) {
    const float* x  = (const float*)d_in[0];
    const int*   ei = (const int*)d_in[1];     // int32 (JAX x64 disabled)
    const float* K  = (const float*)d_in[2];
    const float* Ws = (const float*)d_in[3];
    const float* bs = (const float*)d_in[4];
    const float* Wc = (const float*)d_in[5];
    const float* bc = (const float*)d_in[6];
    const float* W1 = (const float*)d_in[7];
    const float* b1 = (const float*)d_in[8];
    const float* W2 = (const float*)d_in[9];
    const float* b2 = (const float*)d_in[10];
    float* out = (float*)d_out;
    float* R   = out + OUT_OFF;

    k1_g1_R<<<4224, 256>>>(x, ei, K, Ws, bs, R);
    k2_g2_R<<<4224, 256>>>(x, ei, K, Ws, bs, R);
    k3_agg_R<<<4608, 256>>>(x, ei, Ws, bs, R);
    k4_head_R<<<2688, 256>>>(x, Wc, bc, W1, b1, W2, b2, Ws, bs, out, R);
}